// round 6
// baseline (speedup 1.0000x reference)
#include <cuda_runtime.h>
#include <cstdint>
#include <cstddef>

#define N_PULSES 64
#define N_STATES 21
#define THREADS  128
#define WARPS_PER_BLOCK (THREADS / 32)

typedef unsigned long long u64;

// ---- packed f32x2 helpers (FFMA2 in SASS; reachable only via PTX f32x2) ----
__device__ __forceinline__ u64 pk(float lo, float hi) {
    u64 r; asm("mov.b64 %0,{%1,%2};" : "=l"(r) : "f"(lo), "f"(hi)); return r;
}
__device__ __forceinline__ void upk(u64 v, float& lo, float& hi) {
    asm("mov.b64 {%0,%1},%2;" : "=f"(lo), "=f"(hi) : "l"(v));
}
__device__ __forceinline__ u64 fma2(u64 a, u64 b, u64 c) {
    u64 d; asm("fma.rn.f32x2 %0,%1,%2,%3;" : "=l"(d) : "l"(a), "l"(b), "l"(c)); return d;
}
__device__ __forceinline__ u64 mul2(u64 a, u64 b) {
    u64 d; asm("mul.rn.f32x2 %0,%1,%2;" : "=l"(d) : "l"(a), "l"(b)); return d;
}

// TR scalar: int 500 reads small; float 500.0f bit pattern reads huge -> float.
__device__ __forceinline__ float read_scalar(const void* p)
{
    int iv = *(const int*)p;
    if (iv > 0 && iv < 1000000) return (float)iv;
    return *(const float*)p;
}

// NB > 0: compile-time batch size (store offsets fold to STG immediates).
template<int NB>
__global__ __launch_bounds__(THREADS, 6)
void epg_kernel(const float* __restrict__ flip,
                const float* __restrict__ phases,
                const float* __restrict__ T1,
                const float* __restrict__ T2,
                const float* __restrict__ B0,
                const float* __restrict__ B1,
                const void*  __restrict__ TRp,
                float* __restrict__ out,
                int nbatch_dyn)
{
    const int nbatch = (NB > 0) ? NB : nbatch_dyn;
    constexpr size_t CS = (NB > 0) ? (size_t)NB * N_STATES : 1;   // used only when NB>0
    const size_t cs = (size_t)nbatch * N_STATES;

    // [0]=cb [1]=c2b [2]=s2b [3]=-sb [4]=-cb [5]=-c2b [6]=-s2b [7]=pad
    __shared__ __align__(16) u64 s_tp[N_PULSES][8];
    // Per (t, warp, chain): {sa^2 pair, ca*sa pair} -> one LDS.128
    __shared__ __align__(16) u64 s_ab[N_PULSES * WARPS_PER_BLOCK * 2][2];

    const int tid = threadIdx.x;

    if (tid < N_PULSES) {
        float b = phases[tid];
        float sb, cb;
        sincosf(b, &sb, &cb);                 // precise, once per block
        float c2b = cb * cb - sb * sb;
        float s2b = 2.0f * cb * sb;
        s_tp[tid][0] = pk(cb, cb);
        s_tp[tid][1] = pk(c2b, c2b);
        s_tp[tid][2] = pk(s2b, s2b);
        s_tp[tid][3] = pk(-sb, -sb);
        s_tp[tid][4] = pk(-cb, -cb);
        s_tp[tid][5] = pk(-c2b, -c2b);
        s_tp[tid][6] = pk(-s2b, -s2b);
        s_tp[tid][7] = 0ull;
    }
    // RF-angle table: alpha/2 trig per (t, warp, chain), both packed halves
    {
        const int blockbase = blockIdx.x * (WARPS_PER_BLOCK * 4);
        for (int e = tid; e < N_PULSES * WARPS_PER_BLOCK * 2; e += THREADS) {
            int t = e >> 3;
            int r = e & 7;
            int w = r >> 1;
            int c = r & 1;
            int bb = blockbase + w * 4 + c * 2;
            int i0 = (bb     < nbatch) ? bb     : nbatch - 1;
            int i1 = (bb + 1 < nbatch) ? bb + 1 : nbatch - 1;
            float a = flip[t];
            float sa0, ca0, sa1, ca1;
            __sincosf(a * 0.5f * B1[i0], &sa0, &ca0);   // arg in [0,~1.9]
            __sincosf(a * 0.5f * B1[i1], &sa1, &ca1);
            s_ab[e][0] = pk(sa0 * sa0, sa1 * sa1);
            s_ab[e][1] = pk(ca0 * sa0, ca1 * sa1);
        }
    }
    __syncthreads();

    const int lane = tid & 31;
    const int warp = tid >> 5;
    const int base = (blockIdx.x * WARPS_PER_BLOCK + warp) * 4;
    if (base >= nbatch) return;

    const int  iA0 = base;
    const int  iA1 = (base + 1 < nbatch) ? base + 1 : base;
    const bool hiA = (base + 1 < nbatch);
    const bool okB = (base + 2 < nbatch);
    const int  iB0 = okB ? base + 2 : base;
    const int  iB1 = (base + 3 < nbatch) ? base + 3 : iB0;
    const bool hiB = (base + 3 < nbatch);

    const float TR = read_scalar(TRp);
    const float TWO_PI_ML = 2.0f * 3.14159265358979f * 0.001f;

#define MK_CONST(S, i0, i1)                                                    \
    const float E1a##S = expf(-TR / T1[i0]), E1b##S = expf(-TR / T1[i1]);      \
    const float E2a##S = expf(-TR / T2[i0]), E2b##S = expf(-TR / T2[i1]);      \
    float spa##S, cpa##S, spb##S, cpb##S;                                      \
    sincosf(TWO_PI_ML * B0[i0] * TR, &spa##S, &cpa##S);                        \
    sincosf(TWO_PI_ML * B0[i1] * TR, &spb##S, &cpb##S);                        \
    const u64 E1p##S  = pk(E1a##S, E1b##S);                                    \
    const u64 cpr##S  = pk(E2a##S * cpa##S,  E2b##S * cpb##S);                 \
    const u64 cpi##S  = pk(E2a##S * spa##S,  E2b##S * spb##S);                 \
    const u64 cpin##S = pk(-E2a##S * spa##S, -E2b##S * spb##S);                \
    const u64 zadd##S = (lane == 0) ? pk(1.0f - E1a##S, 1.0f - E1b##S) : 0ull;

    MK_CONST(A, iA0, iA1)
    MK_CONST(B, iB0, iB1)
#undef MK_CONST

    const u64 m1p  = pk(-1.0f, -1.0f);
    const u64 m2p  = pk(-2.0f, -2.0f);
    const u64 onep = pk(1.0f, 1.0f);

    // Edge masks (replace SELs with fma-pipe multiplies)
    const u64 maskFp = (lane == 0 || lane >= N_STATES)  ? 0ull : pk(1.0f, 1.0f);
    const u64 maskFm = (lane >= N_STATES - 1)           ? 0ull : pk(1.0f, 1.0f);

    // Store predicates (uint 0/1), warp-edge aware
    const bool active = (lane < N_STATES);
    const uint32_t pAlo = active ? 1u : 0u;
    const uint32_t pAhi = (active && hiA) ? 1u : 0u;
    const uint32_t pBlo = (active && okB) ? 1u : 0u;
    const uint32_t pBhi = (active && hiB) ? 1u : 0u;

    // Packed state
    u64 FprA = 0ull, FpiA = 0ull, FmrA = 0ull, FmiA = 0ull;
    u64 FprB = 0ull, FpiB = 0ull, FmrB = 0ull, FmiB = 0ull;
    u64 ZA = (lane == 0) ? pk(1.0f, 1.0f) : 0ull;
    u64 ZB = ZA;

    float* ot = out + (size_t)iA0 * N_STATES + lane;   // [t][c][batch][state]

#define ADVANCE(S, ABIDX, Fpn, Fpi_n, Fmn, Fmi_n, Zn)                          \
    u64 Fpn, Fpi_n, Fmn, Fmi_n, Zn;                                            \
    {                                                                          \
        const ulonglong2 sc =                                                  \
            *(const ulonglong2*)&s_ab[(t * WARPS_PER_BLOCK + warp) * 2 + (ABIDX)][0]; \
        const u64 sa2p = sc.x, casap = sc.y;                                   \
        const u64 zr  = fma2(E1p##S, Z##S, zadd##S);                           \
        const u64 npr = fma2(cpr##S, Fpr##S, mul2(cpin##S, Fpi##S));           \
        const u64 npi = fma2(cpr##S, Fpi##S, mul2(cpi##S,  Fpr##S));           \
        const u64 nmr = fma2(cpr##S, Fmr##S, mul2(cpi##S,  Fmi##S));           \
        const u64 nmi = fma2(cpr##S, Fmi##S, mul2(cpin##S, Fmr##S));           \
        const u64 ca2p = fma2(sa2p, m1p, onep);      /* ca^2 = 1 - sa^2 */     \
        const u64 k7   = fma2(sa2p, m2p, onep);      /* ca^2 - sa^2 */         \
        const u64 k1  = mul2(sa2p, tp1);                                       \
        const u64 k2  = mul2(sa2p, tp2);                                       \
        const u64 k1n = mul2(sa2p, tp5);                                       \
        const u64 k2n = mul2(sa2p, tp6);                                       \
        const u64 k3n = mul2(casap, tp3);                                      \
        const u64 k4  = mul2(casap, tp0);                                      \
        const u64 k4n = mul2(casap, tp4);                                      \
        Fpn   = fma2(k3n, zr, fma2(k2,  nmi, fma2(k1,  nmr, mul2(ca2p, npr))));\
        Fpi_n = fma2(k4,  zr, fma2(k1n, nmi, fma2(k2,  nmr, mul2(ca2p, npi))));\
        Fmn   = fma2(k3n, zr, fma2(ca2p, nmr, fma2(k2n, npi, mul2(k1, npr)))); \
        Fmi_n = fma2(k4n, zr, fma2(ca2p, nmi, fma2(k1n, npi, mul2(k2n, npr))));\
        Zn    = fma2(k7,  zr, fma2(k3n, nmr, fma2(k3n, npr,                    \
                                  fma2(k4n, nmi, mul2(k4, npi)))));            \
    }

    // One setp + 5 predicated stores with literal immediate offsets (bytes).
#define PSTG5(V0, V1, V2, V3, V4, PRD, OFF)                                    \
    asm volatile("{\n\t.reg .pred p;\n\t"                                      \
        "setp.ne.u32 p, %6, 0;\n\t"                                            \
        "@p st.global.f32 [%0+%7],  %1;\n\t"                                   \
        "@p st.global.f32 [%0+%8],  %2;\n\t"                                   \
        "@p st.global.f32 [%0+%9],  %3;\n\t"                                   \
        "@p st.global.f32 [%0+%10], %4;\n\t"                                   \
        "@p st.global.f32 [%0+%11], %5;\n\t}"                                  \
        :: "l"(ot), "f"(V0), "f"(V1), "f"(V2), "f"(V3), "f"(V4), "r"(PRD),     \
           "n"((long)((OFF)) * 4),            "n"((long)((OFF) + CS) * 4),     \
           "n"((long)((OFF) + 2 * CS) * 4),   "n"((long)((OFF) + 3 * CS) * 4), \
           "n"((long)((OFF) + 4 * CS) * 4)                                     \
        : "memory")

#pragma unroll 1
    for (int t = 0; t < N_PULSES; ++t) {
        const ulonglong2* tpv = (const ulonglong2*)&s_tp[t][0];
        const ulonglong2 tq0 = tpv[0], tq1 = tpv[1], tq2 = tpv[2], tq3 = tpv[3];
        const u64 tp0 = tq0.x, tp1 = tq0.y, tp2 = tq1.x, tp3 = tq1.y;
        const u64 tp4 = tq2.x, tp5 = tq2.y, tp6 = tq3.x;
        (void)tq3.y;

        // --- chain A compute, then launch its shuffles ---
        ADVANCE(A, 0, FpnA, FpinA, FmnA, FminA, ZnA)
        u64 sFprA = __shfl_up_sync(0xffffffffu, FpnA, 1);
        u64 sFpiA = __shfl_up_sync(0xffffffffu, FpinA, 1);
        u64 sFmrA = __shfl_down_sync(0xffffffffu, FmnA, 1);
        u64 sFmiA = __shfl_down_sync(0xffffffffu, FminA, 1);

        // --- chain B compute fills chain A's shuffle latency ---
        ADVANCE(B, 1, FpnB, FpinB, FmnB, FminB, ZnB)
        u64 sFprB = __shfl_up_sync(0xffffffffu, FpnB, 1);
        u64 sFpiB = __shfl_up_sync(0xffffffffu, FpinB, 1);
        u64 sFmrB = __shfl_down_sync(0xffffffffu, FmnB, 1);
        u64 sFmiB = __shfl_down_sync(0xffffffffu, FminB, 1);

        // Edge zeroing as mask multiplies (no SELs)
        FprA = mul2(sFprA, maskFp); FpiA = mul2(sFpiA, maskFp);
        FmrA = mul2(sFmrA, maskFm); FmiA = mul2(sFmiA, maskFm);
        FprB = mul2(sFprB, maskFp); FpiB = mul2(sFpiB, maskFp);
        FmrB = mul2(sFmrB, maskFm); FmiB = mul2(sFmiB, maskFm);
        ZA = ZnA; ZB = ZnB;

        float al0,ah0,al1,ah1,al2,ah2,al3,ah3,al4,ah4;
        upk(FprA,al0,ah0); upk(FpiA,al1,ah1); upk(FmrA,al2,ah2);
        upk(FmiA,al3,ah3); upk(ZnA, al4,ah4);
        float bl0,bh0,bl1,bh1,bl2,bh2,bl3,bh3,bl4,bh4;
        upk(FprB,bl0,bh0); upk(FpiB,bl1,bh1); upk(FmrB,bl2,bh2);
        upk(FmiB,bl3,bh3); upk(ZnB, bl4,bh4);

        if constexpr (NB > 0) {
            PSTG5(al0, al1, al2, al3, al4, pAlo, 0);
            PSTG5(ah0, ah1, ah2, ah3, ah4, pAhi, N_STATES);
            PSTG5(bl0, bl1, bl2, bl3, bl4, pBlo, 2 * N_STATES);
            PSTG5(bh0, bh1, bh2, bh3, bh4, pBhi, 3 * N_STATES);
        } else {
            if (active) {
                ot[0] = al0; ot[cs] = al1; ot[2*cs] = al2; ot[3*cs] = al3; ot[4*cs] = al4;
                if (hiA) {
                    ot[N_STATES] = ah0; ot[N_STATES+cs] = ah1; ot[N_STATES+2*cs] = ah2;
                    ot[N_STATES+3*cs] = ah3; ot[N_STATES+4*cs] = ah4;
                }
                if (okB) {
                    ot[2*N_STATES] = bl0; ot[2*N_STATES+cs] = bl1; ot[2*N_STATES+2*cs] = bl2;
                    ot[2*N_STATES+3*cs] = bl3; ot[2*N_STATES+4*cs] = bl4;
                }
                if (hiB) {
                    ot[3*N_STATES] = bh0; ot[3*N_STATES+cs] = bh1; ot[3*N_STATES+2*cs] = bh2;
                    ot[3*N_STATES+3*cs] = bh3; ot[3*N_STATES+4*cs] = bh4;
                }
            }
        }
        ot += 5u * ((NB > 0) ? CS : cs);
    }
#undef ADVANCE
#undef PSTG5
}

extern "C" void kernel_launch(void* const* d_in, const int* in_sizes, int n_in,
                              void* d_out, int out_size)
{
    const float* flip   = (const float*)d_in[0];
    const float* phases = (const float*)d_in[1];
    const float* T1     = (const float*)d_in[2];
    const float* T2     = (const float*)d_in[3];
    const float* B0     = (const float*)d_in[4];
    const float* B1     = (const float*)d_in[5];
    const void*  TRp    = d_in[6];

    const int nbatch = in_sizes[2];          // T1 element count = batch
    float* out = (float*)d_out;
    const int nwarps = (nbatch + 3) / 4;     // 4 batches per warp (2 chains)
    const int blocks = (nwarps + WARPS_PER_BLOCK - 1) / WARPS_PER_BLOCK;

    if (nbatch == 16384) {
        epg_kernel<16384><<<blocks, THREADS>>>(flip, phases, T1, T2, B0, B1,
                                               TRp, out, nbatch);
    } else {
        epg_kernel<0><<<blocks, THREADS>>>(flip, phases, T1, T2, B0, B1,
                                           TRp, out, nbatch);
    }
}

// round 8
// speedup vs baseline: 1.4997x; 1.4997x over previous
#include <cuda_runtime.h>
#include <cstdint>

#define N_PULSES 64
#define N_STATES 21
#define THREADS  256
#define WARPS_PER_BLOCK (THREADS / 32)

typedef unsigned long long u64;

// ---- packed f32x2 helpers (FFMA2 in SASS; reachable only via PTX f32x2) ----
__device__ __forceinline__ u64 pk(float lo, float hi) {
    u64 r; asm("mov.b64 %0,{%1,%2};" : "=l"(r) : "f"(lo), "f"(hi)); return r;
}
__device__ __forceinline__ void upk(u64 v, float& lo, float& hi) {
    asm("mov.b64 {%0,%1},%2;" : "=f"(lo), "=f"(hi) : "l"(v));
}
__device__ __forceinline__ u64 fma2(u64 a, u64 b, u64 c) {
    u64 d; asm("fma.rn.f32x2 %0,%1,%2,%3;" : "=l"(d) : "l"(a), "l"(b), "l"(c)); return d;
}
__device__ __forceinline__ u64 mul2(u64 a, u64 b) {
    u64 d; asm("mul.rn.f32x2 %0,%1,%2;" : "=l"(d) : "l"(a), "l"(b)); return d;
}

// TR scalar: int 500 reads small; float 500.0f bit pattern reads huge -> float.
__device__ __forceinline__ float read_scalar(const void* p)
{
    int iv = *(const int*)p;
    if (iv > 0 && iv < 1000000) return (float)iv;
    return *(const float*)p;
}

__global__ __launch_bounds__(THREADS, 1)
void epg_kernel(const float* __restrict__ flip,
                const float* __restrict__ phases,
                const float* __restrict__ T1,
                const float* __restrict__ T2,
                const float* __restrict__ B0,
                const float* __restrict__ B1,
                const void*  __restrict__ TRp,
                float* __restrict__ out,
                int nbatch)
{
    // Broadcast-packed trig table (batch-independent, shared by both chains):
    // [0]=cb, [1]=c2b, [2]=s2b, [3]=-sb, [4]=-cb, [5]=-c2b, [6]=-s2b, [7]=pad
    __shared__ __align__(16) u64 s_tp[N_PULSES][8];
    // RF-angle table per (t, warp, chain): {sa^2 pair, ca*sa pair} -> 1 LDS.128
    __shared__ __align__(16) u64 s_ab[N_PULSES * WARPS_PER_BLOCK * 2][2];

    const int tid = threadIdx.x;
    if (tid < N_PULSES) {
        float b = phases[tid];
        float sb, cb;
        sincosf(b, &sb, &cb);                 // precise, once per block
        float c2b = cb * cb - sb * sb;
        float s2b = 2.0f * cb * sb;
        s_tp[tid][0] = pk(cb, cb);
        s_tp[tid][1] = pk(c2b, c2b);
        s_tp[tid][2] = pk(s2b, s2b);
        s_tp[tid][3] = pk(-sb, -sb);
        s_tp[tid][4] = pk(-cb, -cb);
        s_tp[tid][5] = pk(-c2b, -c2b);
        s_tp[tid][6] = pk(-s2b, -s2b);
        s_tp[tid][7] = 0ull;
    }
    // Hoist ALL per-step sincos out of the hot loop (MUFU was 4x oversubscribed)
    {
        const int blockbase = blockIdx.x * (WARPS_PER_BLOCK * 4);
        for (int e = tid; e < N_PULSES * WARPS_PER_BLOCK * 2; e += THREADS) {
            int t = e >> 4;                  // WARPS_PER_BLOCK*2 = 16 entries per t
            int r = e & 15;
            int w = r >> 1;
            int c = r & 1;
            int bb = blockbase + w * 4 + c * 2;
            int i0 = (bb     < nbatch) ? bb     : nbatch - 1;
            int i1 = (bb + 1 < nbatch) ? bb + 1 : nbatch - 1;
            float a = flip[t];
            float sa0, ca0, sa1, ca1;
            __sincosf(a * 0.5f * B1[i0], &sa0, &ca0);   // arg in [0,~1.9] fast-path
            __sincosf(a * 0.5f * B1[i1], &sa1, &ca1);
            s_ab[e][0] = pk(sa0 * sa0, sa1 * sa1);
            s_ab[e][1] = pk(ca0 * sa0, ca1 * sa1);
        }
    }
    __syncthreads();

    const int lane = tid & 31;
    const int warp = tid >> 5;
    const int base = (blockIdx.x * WARPS_PER_BLOCK + warp) * 4;
    if (base >= nbatch) return;

    // Chain A: batches base, base+1.  Chain B: batches base+2, base+3.
    const int  iA0 = base;
    const int  iA1 = (base + 1 < nbatch) ? base + 1 : base;
    const bool hiA = (base + 1 < nbatch);
    const bool okB = (base + 2 < nbatch);
    const int  iB0 = okB ? base + 2 : base;
    const int  iB1 = (base + 3 < nbatch) ? base + 3 : iB0;
    const bool hiB = (base + 3 < nbatch);

    const float TR = read_scalar(TRp);
    const float TWO_PI_ML = 2.0f * 3.14159265358979f * 0.001f;

#define MK_CONST(S, i0, i1)                                                    \
    const float E1a##S = expf(-TR / T1[i0]), E1b##S = expf(-TR / T1[i1]);      \
    const float E2a##S = expf(-TR / T2[i0]), E2b##S = expf(-TR / T2[i1]);      \
    float spa##S, cpa##S, spb##S, cpb##S;                                      \
    sincosf(TWO_PI_ML * B0[i0] * TR, &spa##S, &cpa##S);                        \
    sincosf(TWO_PI_ML * B0[i1] * TR, &spb##S, &cpb##S);                        \
    const u64 E1p##S  = pk(E1a##S, E1b##S);                                    \
    const u64 cpr##S  = pk(E2a##S * cpa##S,  E2b##S * cpb##S);                 \
    const u64 cpi##S  = pk(E2a##S * spa##S,  E2b##S * spb##S);                 \
    const u64 cpin##S = pk(-E2a##S * spa##S, -E2b##S * spb##S);                \
    const u64 zadd##S = (lane == 0) ? pk(1.0f - E1a##S, 1.0f - E1b##S) : 0ull;

    MK_CONST(A, iA0, iA1)
    MK_CONST(B, iB0, iB1)
#undef MK_CONST

    const u64 m1p  = pk(-1.0f, -1.0f);
    const u64 m2p  = pk(-2.0f, -2.0f);
    const u64 onep = pk(1.0f, 1.0f);

    // Packed state (lane = EPG order; lanes >= 21 stay exactly zero)
    u64 FprA = 0ull, FpiA = 0ull, FmrA = 0ull, FmiA = 0ull;
    u64 FprB = 0ull, FpiB = 0ull, FmrB = 0ull, FmiB = 0ull;
    u64 ZA = (lane == 0) ? pk(1.0f, 1.0f) : 0ull;
    u64 ZB = ZA;

    const size_t cs = (size_t)nbatch * N_STATES;            // component stride
    float* oA = out + (size_t)iA0 * N_STATES + lane;        // [t][c][batch][state]
    const bool active = (lane < N_STATES);
    const bool edgeFp = (lane == 0 || lane >= N_STATES);
    const bool edgeFm = (lane >= N_STATES - 1);

#define ADVANCE(S, ABIDX, Fpn, Fpi_n, Fmn, Fmi_n, Zn)                          \
    u64 Fpn, Fpi_n, Fmn, Fmi_n, Zn;                                            \
    {                                                                          \
        const ulonglong2 sc =                                                  \
            *(const ulonglong2*)&s_ab[(t * WARPS_PER_BLOCK + warp) * 2 + (ABIDX)][0]; \
        const u64 sa2p = sc.x, casap = sc.y;                                   \
        const u64 zr  = fma2(E1p##S, Z##S, zadd##S);                           \
        const u64 npr = fma2(cpr##S, Fpr##S, mul2(cpin##S, Fpi##S));           \
        const u64 npi = fma2(cpr##S, Fpi##S, mul2(cpi##S,  Fpr##S));           \
        const u64 nmr = fma2(cpr##S, Fmr##S, mul2(cpi##S,  Fmi##S));           \
        const u64 nmi = fma2(cpr##S, Fmi##S, mul2(cpin##S, Fmr##S));           \
        const u64 ca2p = fma2(sa2p, m1p, onep);      /* ca^2 = 1 - sa^2 */     \
        const u64 k7   = fma2(sa2p, m2p, onep);      /* ca^2 - sa^2 */         \
        const u64 k1  = mul2(sa2p, tp1);                                       \
        const u64 k2  = mul2(sa2p, tp2);                                       \
        const u64 k1n = mul2(sa2p, tp5);                                       \
        const u64 k2n = mul2(sa2p, tp6);                                       \
        const u64 k3n = mul2(casap, tp3);                                      \
        const u64 k4  = mul2(casap, tp0);                                      \
        const u64 k4n = mul2(casap, tp4);                                      \
        Fpn   = fma2(k3n, zr, fma2(k2,  nmi, fma2(k1,  nmr, mul2(ca2p, npr))));\
        Fpi_n = fma2(k4,  zr, fma2(k1n, nmi, fma2(k2,  nmr, mul2(ca2p, npi))));\
        Fmn   = fma2(k3n, zr, fma2(ca2p, nmr, fma2(k2n, npi, mul2(k1, npr)))); \
        Fmi_n = fma2(k4n, zr, fma2(ca2p, nmi, fma2(k1n, npi, mul2(k2n, npr))));\
        Zn    = fma2(k7,  zr, fma2(k3n, nmr, fma2(k3n, npr,                    \
                                  fma2(k4n, nmi, mul2(k4, npi)))));            \
    }

#define STORE5(ptr, v0, v1, v2, v3, v4, off, half)                             \
    {                                                                          \
        float l0,h0,l1,h1,l2,h2,l3,h3,l4,h4;                                   \
        upk(v0,l0,h0); upk(v1,l1,h1); upk(v2,l2,h2);                           \
        upk(v3,l3,h3); upk(v4,l4,h4);                                          \
        (ptr)[(off)]          = l0;                                            \
        (ptr)[(off) + cs]     = l1;                                            \
        (ptr)[(off) + 2*cs]   = l2;                                            \
        (ptr)[(off) + 3*cs]   = l3;                                            \
        (ptr)[(off) + 4*cs]   = l4;                                            \
        if (half) {                                                            \
            (ptr)[(off) + N_STATES]        = h0;                               \
            (ptr)[(off) + N_STATES + cs]   = h1;                               \
            (ptr)[(off) + N_STATES + 2*cs] = h2;                               \
            (ptr)[(off) + N_STATES + 3*cs] = h3;                               \
            (ptr)[(off) + N_STATES + 4*cs] = h4;                               \
        }                                                                      \
    }

#pragma unroll 1
    for (int t = 0; t < N_PULSES; ++t) {
        const ulonglong2* tpv = (const ulonglong2*)&s_tp[t][0];
        const ulonglong2 tq0 = tpv[0], tq1 = tpv[1], tq2 = tpv[2], tq3 = tpv[3];
        const u64 tp0 = tq0.x, tp1 = tq0.y, tp2 = tq1.x, tp3 = tq1.y;
        const u64 tp4 = tq2.x, tp5 = tq2.y, tp6 = tq3.x;
        (void)tq3;

        // --- chain A compute, then launch its shuffles ---
        ADVANCE(A, 0, FpnA, FpinA, FmnA, FminA, ZnA)
        u64 sFprA = __shfl_up_sync(0xffffffffu, FpnA, 1);
        u64 sFpiA = __shfl_up_sync(0xffffffffu, FpinA, 1);
        u64 sFmrA = __shfl_down_sync(0xffffffffu, FmnA, 1);
        u64 sFmiA = __shfl_down_sync(0xffffffffu, FminA, 1);

        // --- chain B compute fills chain A's shuffle latency ---
        ADVANCE(B, 1, FpnB, FpinB, FmnB, FminB, ZnB)
        u64 sFprB = __shfl_up_sync(0xffffffffu, FpnB, 1);
        u64 sFpiB = __shfl_up_sync(0xffffffffu, FpinB, 1);
        u64 sFmrB = __shfl_down_sync(0xffffffffu, FmnB, 1);
        u64 sFmiB = __shfl_down_sync(0xffffffffu, FminB, 1);

        if (edgeFp) { sFprA = 0ull; sFpiA = 0ull; sFprB = 0ull; sFpiB = 0ull; }
        if (edgeFm) { sFmrA = 0ull; sFmiA = 0ull; sFmrB = 0ull; sFmiB = 0ull; }
        FprA = sFprA; FpiA = sFpiA; FmrA = sFmrA; FmiA = sFmiA; ZA = ZnA;
        FprB = sFprB; FpiB = sFpiB; FmrB = sFmrB; FmiB = sFmiB; ZB = ZnB;

        if (active) {
            float* ot = oA + (size_t)t * 5u * cs;
            STORE5(ot, FprA, FpiA, FmrA, FmiA, ZnA, 0, hiA)
            if (okB)
                STORE5(ot, FprB, FpiB, FmrB, FmiB, ZnB, 2 * N_STATES, hiB)
        }
    }
#undef ADVANCE
#undef STORE5
}

extern "C" void kernel_launch(void* const* d_in, const int* in_sizes, int n_in,
                              void* d_out, int out_size)
{
    const float* flip   = (const float*)d_in[0];
    const float* phases = (const float*)d_in[1];
    const float* T1     = (const float*)d_in[2];
    const float* T2     = (const float*)d_in[3];
    const float* B0     = (const float*)d_in[4];
    const float* B1     = (const float*)d_in[5];
    const void*  TRp    = d_in[6];

    const int nbatch = in_sizes[2];          // T1 element count = batch
    float* out = (float*)d_out;
    const int nwarps = (nbatch + 3) / 4;     // 4 batches per warp (2 chains)
    const int blocks = (nwarps + WARPS_PER_BLOCK - 1) / WARPS_PER_BLOCK;
    epg_kernel<<<blocks, THREADS>>>(flip, phases, T1, T2, B0, B1, TRp, out, nbatch);
}